// round 1
// baseline (speedup 1.0000x reference)
#include <cuda_runtime.h>
#include <math.h>

// Problem constants
#define BATCH 1024
#define DDIM  64
#define MNUM  3
#define CNUM  16384
#define NBR   2

// Tiling
#define TC  128      // centroid tile
#define TB  128      // feature tile
#define PAD 65       // smem row stride (floats) -> conflict-friendly scalar LDS

// Scratch: per-(branch,m,b) sum of exp(logit). 2*3*1024 = 6144 floats.
__device__ float g_S[NBR * MNUM * BATCH];

__global__ void init_kernel() {
    int i = blockIdx.x * blockDim.x + threadIdx.x;
    if (i < NBR * MNUM * BATCH) g_S[i] = 0.0f;
}

// Each block: one (branch, m, cTile, bTile). Computes 128x128 dots (D=64),
// applies exp via FMA-only polynomial (MUFU-free), reduces over the 128 c's,
// and atomically accumulates 128 per-b partial sums into g_S.
__global__ __launch_bounds__(256, 2)
void gemm_exp_kernel(const float* __restrict__ cen,  const float* __restrict__ cenI,
                     const float* __restrict__ f,    const float* __restrict__ fI,
                     const float* __restrict__ conc, const float* __restrict__ concI)
{
    extern __shared__ float sm[];
    float* sc   = sm;                 // [TC][PAD] centroid tile
    float* sf   = sm + TC * PAD;      // [TB][PAD] feature tile
    float* inv4 = sm + 2 * TC * PAD;  // [TC] 1/(4*conc)
    float* red  = sm;                 // reduction buffer, aliases sc after sync

    const int cT = blockIdx.x;
    const int bT = blockIdx.y;
    const int z  = blockIdx.z;
    const int branch = (z >= MNUM) ? 1 : 0;
    const int m      = branch ? (z - MNUM) : z;

    // branch 0: loss(M_kmeans, features_I, concentrations)
    // branch 1: loss(M_kmeans_I, features, concentrations_I)
    const float* cenP  = branch ? cenI  : cen;
    const float* featP = branch ? f     : fI;
    const float* concP = branch ? concI : conc;

    const int tid = threadIdx.x;

    const float* gc = cenP  + ((size_t)(m * CNUM + cT * TC)) * DDIM;
    const float* gf = featP + (size_t)bT * TB * DDIM;

    // Load both 128x64 fp32 tiles: float4 LDG, scalar STS (pad keeps <=~2-way)
    #pragma unroll
    for (int it = 0; it < 8; it++) {
        int q   = tid + 256 * it;          // float4 index, 2048 total per tile
        int row = q >> 4;
        int d   = (q & 15) << 2;
        float4 v = *(const float4*)(gc + row * DDIM + d);
        float* dc = sc + row * PAD + d;
        dc[0] = v.x; dc[1] = v.y; dc[2] = v.z; dc[3] = v.w;
        float4 w = *(const float4*)(gf + row * DDIM + d);
        float* df = sf + row * PAD + d;
        df[0] = w.x; df[1] = w.y; df[2] = w.z; df[3] = w.w;
    }
    if (tid < TC) inv4[tid] = 0.25f / concP[m * CNUM + cT * TC + tid];
    __syncthreads();

    const int ty = tid >> 4;   // 0..15 -> c sub-rows ty + 16*i
    const int tx = tid & 15;   // 0..15 -> b sub-cols tx + 16*j

    float acc[8][8];
    #pragma unroll
    for (int i = 0; i < 8; i++)
        #pragma unroll
        for (int j = 0; j < 8; j++) acc[i][j] = 0.0f;

    const float* pA = sc + ty * PAD;
    const float* pB = sf + tx * PAD;

    #pragma unroll 8
    for (int k = 0; k < DDIM; k++) {
        float a[8], b[8];
        #pragma unroll
        for (int i = 0; i < 8; i++) a[i] = pA[i * 16 * PAD + k];
        #pragma unroll
        for (int j = 0; j < 8; j++) b[j] = pB[j * 16 * PAD + k];
        #pragma unroll
        for (int i = 0; i < 8; i++)
            #pragma unroll
            for (int j = 0; j < 8; j++)
                acc[i][j] = fmaf(a[i], b[j], acc[i][j]);
    }

    float invr[8];
    #pragma unroll
    for (int i = 0; i < 8; i++) invr[i] = inv4[ty + 16 * i];

    // exp(z) = (e^{z/4})^4, z/4 in [-0.5,0.5]; degree-6 Taylor, FMA-only.
    const float c6 = 1.0f / 720.0f, c5 = 1.0f / 120.0f, c4 = 1.0f / 24.0f;
    const float c3 = 1.0f / 6.0f,   c2 = 0.5f;

    float part[8];
    #pragma unroll
    for (int j = 0; j < 8; j++) part[j] = 0.0f;

    #pragma unroll
    for (int i = 0; i < 8; i++)
        #pragma unroll
        for (int j = 0; j < 8; j++) {
            float x = acc[i][j] * invr[i];        // dot/(4*conc)
            float p = fmaf(x, c6, c5);
            p = fmaf(x, p, c4);
            p = fmaf(x, p, c3);
            p = fmaf(x, p, c2);
            p = fmaf(x, p, 1.0f);
            p = fmaf(x, p, 1.0f);
            p = p * p;
            p = p * p;                            // e^{dot/conc}
            part[j] += p;
        }

    __syncthreads();   // tiles no longer needed; red aliases sc
    #pragma unroll
    for (int j = 0; j < 8; j++)
        red[(tx * 8 + j) * 17 + ty] = part[j];
    __syncthreads();

    if (tid < TB) {
        float s = 0.0f;
        #pragma unroll
        for (int t = 0; t < 16; t++) s += red[tid * 17 + t];
        atomicAdd(&g_S[(branch * MNUM + m) * BATCH + bT * TB + tid], s);
    }
}

// Single block: positive logits + log(S) + full deterministic reduction + scale.
__global__ void finalize_kernel(const float* __restrict__ cen,  const float* __restrict__ cenI,
                                const float* __restrict__ f,    const float* __restrict__ fI,
                                const float* __restrict__ conc, const float* __restrict__ concI,
                                const int* __restrict__ lab,    const int* __restrict__ labI,
                                const int* __restrict__ lb,     float* __restrict__ out)
{
    __shared__ float sred[1024];
    const int tid = threadIdx.x;
    float acc = 0.0f;

    for (int idx = tid; idx < NBR * MNUM * BATCH; idx += 1024) {
        int branch = idx / (MNUM * BATCH);
        int r = idx - branch * MNUM * BATCH;
        int m = r / BATCH;
        int b = r - m * BATCH;

        const float* cenP  = branch ? cenI  : cen;
        const float* featP = branch ? f     : fI;
        const float* concP = branch ? concI : conc;
        const int*   labP  = branch ? labI  : lab;

        int c = labP[m * BATCH + b];
        const float4* cr = (const float4*)(cenP + ((size_t)(m * CNUM) + c) * DDIM);
        const float4* fr = (const float4*)(featP + (size_t)b * DDIM);
        float dot = 0.0f;
        #pragma unroll
        for (int d = 0; d < 16; d++) {
            float4 a = cr[d];
            float4 w = fr[d];
            dot += a.x * w.x + a.y * w.y + a.z * w.z + a.w * w.w;
        }
        float logit = dot / concP[m * CNUM + c];
        acc += logit - logf(g_S[idx]);       // log(pos/sum) = logit_pos - log(S)
    }

    sred[tid] = acc;
    __syncthreads();
    for (int s = 512; s > 0; s >>= 1) {
        if (tid < s) sred[tid] += sred[tid + s];
        __syncthreads();
    }
    if (tid == 0) {
        // (1/B) * lb * (-1/M) * 0.5 * (t + t_I)
        float scale = -(float)lb[0] / (2.0f * (float)BATCH * (float)MNUM);
        out[0] = scale * sred[0];
    }
}

extern "C" void kernel_launch(void* const* d_in, const int* in_sizes, int n_in,
                              void* d_out, int out_size)
{
    const float* f     = (const float*)d_in[0];
    const float* fI    = (const float*)d_in[1];
    const float* cen   = (const float*)d_in[2];
    const float* cenI  = (const float*)d_in[3];
    const float* conc  = (const float*)d_in[4];
    const float* concI = (const float*)d_in[5];
    const int*   lab   = (const int*)d_in[6];
    const int*   labI  = (const int*)d_in[7];
    const int*   lb    = (const int*)d_in[8];
    float* out = (float*)d_out;

    const int smem_bytes = (2 * TC * PAD + TC) * (int)sizeof(float);  // 67,072
    cudaFuncSetAttribute(gemm_exp_kernel,
                         cudaFuncAttributeMaxDynamicSharedMemorySize, smem_bytes);

    init_kernel<<<6, 1024>>>();
    dim3 grid(CNUM / TC, BATCH / TB, NBR * MNUM);
    gemm_exp_kernel<<<grid, 256, smem_bytes>>>(cen, cenI, f, fI, conc, concI);
    finalize_kernel<<<1, 1024>>>(cen, cenI, f, fI, conc, concI, lab, labI, lb, out);
}